// round 1
// baseline (speedup 1.0000x reference)
#include <cuda_runtime.h>
#include <cuda_bf16.h>
#include <math.h>

// Problem constants
#define NR 8192          // N rows (embeddings)
#define DD 1024          // D
#define ITERS 20
#define INV_TEMP 20.0f

// GEMM tiling
#define BM 128
#define BN 128
#define BK 16
#define TM 8
#define TN 8
// 256 threads per block

// Sinkhorn column-pass chunking
#define COL_CHUNKS 64
#define ROWS_PER_CHUNK (NR / COL_CHUNKS)   // 128

// ---------------- device scratch (static, no allocation) ----------------
__device__ float g_scores[(size_t)NR * NR];   // 256 MB
__device__ float g_h[(size_t)NR * DD];        // hidden
__device__ float g_a[(size_t)NR * DD];
__device__ float g_b[(size_t)NR * DD];
__device__ float g_bT[(size_t)DD * NR];
__device__ float g_r[NR];
__device__ float g_c[NR];
__device__ float g_pm[(size_t)COL_CHUNKS * NR];
__device__ float g_ps[(size_t)COL_CHUNKS * NR];

// ---------------- helpers ----------------
__device__ __forceinline__ float gelu_exact(float x) {
    return 0.5f * x * (1.0f + erff(x * 0.70710678118654752440f));
}

__device__ __forceinline__ void lse_add(float& m, float& s, float v) {
    if (v <= m) {
        s += expf(v - m);
    } else {
        s = s * expf(m - v) + 1.0f;   // m==-inf => expf(-inf)=0
        m = v;
    }
}

__device__ __forceinline__ void lse_merge(float& m1, float& s1, float m2, float s2) {
    if (m2 == -INFINITY) return;
    if (m1 == -INFINITY) { m1 = m2; s1 = s2; return; }
    if (m2 <= m1) {
        s1 += s2 * expf(m2 - m1);
    } else {
        s1 = s1 * expf(m1 - m2) + s2;
        m1 = m2;
    }
}

// ---------------- SGEMM: C = act(scale*(A@B) + bias) ----------------
// A: [M,K] row-major, B: [K,N] row-major, C: [M,N] row-major.
// M % BM == 0, N % BN == 0, K % BK == 0 (true for all our shapes).
template <int ACT>
__global__ __launch_bounds__(256, 2)
void sgemm_kernel(int M, int N, int K,
                  const float* __restrict__ A,
                  const float* __restrict__ B,
                  const float* __restrict__ bias,
                  float* __restrict__ C,
                  float scale)
{
    __shared__ float As[BK][BM + 4];   // transposed A tile, padded
    __shared__ float Bs[BK][BN];

    const int cRow = blockIdx.y;
    const int cCol = blockIdx.x;
    const int tid  = threadIdx.x;

    // A-tile loader mapping: BK/4 = 4 float4 per row
    const int innerRowA = tid / 4;       // 0..63
    const int innerColA = tid % 4;       // float4 index within row
    // B-tile loader: BN/4 = 32 float4 per row
    const int innerRowB = tid / 32;      // 0..7
    const int innerColB = tid % 32;

    const int threadRow = tid / (BN / TN);   // 0..15
    const int threadCol = tid % (BN / TN);   // 0..15

    const float* Ab = A + (size_t)cRow * BM * K;
    const float* Bb = B + (size_t)cCol * BN;

    float acc[TM][TN];
#pragma unroll
    for (int i = 0; i < TM; i++)
#pragma unroll
        for (int j = 0; j < TN; j++) acc[i][j] = 0.0f;

    for (int kt = 0; kt < K; kt += BK) {
        // load A tile (BM x BK), store transposed
#pragma unroll
        for (int r = 0; r < BM; r += 64) {
            float4 t = *(const float4*)(&Ab[(size_t)(innerRowA + r) * K + kt + innerColA * 4]);
            As[innerColA * 4 + 0][innerRowA + r] = t.x;
            As[innerColA * 4 + 1][innerRowA + r] = t.y;
            As[innerColA * 4 + 2][innerRowA + r] = t.z;
            As[innerColA * 4 + 3][innerRowA + r] = t.w;
        }
        // load B tile (BK x BN)
#pragma unroll
        for (int r = 0; r < BK; r += 8) {
            *(float4*)(&Bs[innerRowB + r][innerColB * 4]) =
                *(const float4*)(&Bb[(size_t)(kt + innerRowB + r) * N + innerColB * 4]);
        }
        __syncthreads();

#pragma unroll
        for (int k = 0; k < BK; k++) {
            float regM[TM], regN[TN];
            float4 m0 = *(const float4*)(&As[k][threadRow * TM]);
            float4 m1 = *(const float4*)(&As[k][threadRow * TM + 4]);
            regM[0] = m0.x; regM[1] = m0.y; regM[2] = m0.z; regM[3] = m0.w;
            regM[4] = m1.x; regM[5] = m1.y; regM[6] = m1.z; regM[7] = m1.w;
            float4 n0 = *(const float4*)(&Bs[k][threadCol * TN]);
            float4 n1 = *(const float4*)(&Bs[k][threadCol * TN + 4]);
            regN[0] = n0.x; regN[1] = n0.y; regN[2] = n0.z; regN[3] = n0.w;
            regN[4] = n1.x; regN[5] = n1.y; regN[6] = n1.z; regN[7] = n1.w;
#pragma unroll
            for (int i = 0; i < TM; i++)
#pragma unroll
                for (int j = 0; j < TN; j++)
                    acc[i][j] = fmaf(regM[i], regN[j], acc[i][j]);
        }
        __syncthreads();
    }

    // epilogue
#pragma unroll
    for (int i = 0; i < TM; i++) {
        size_t row = (size_t)cRow * BM + threadRow * TM + i;
        float* Crow = C + row * N + (size_t)cCol * BN + threadCol * TN;
#pragma unroll
        for (int j = 0; j < TN; j += 4) {
            int col = cCol * BN + threadCol * TN + j;
            float4 v;
            v.x = acc[i][j + 0] * scale;
            v.y = acc[i][j + 1] * scale;
            v.z = acc[i][j + 2] * scale;
            v.w = acc[i][j + 3] * scale;
            if (bias) {
                float4 bb = *(const float4*)(&bias[col]);
                v.x += bb.x; v.y += bb.y; v.z += bb.z; v.w += bb.w;
            }
            if (ACT == 1) {
                v.x = gelu_exact(v.x); v.y = gelu_exact(v.y);
                v.z = gelu_exact(v.z); v.w = gelu_exact(v.w);
            }
            *(float4*)(&Crow[j]) = v;
        }
    }
}

// ---------------- transpose: out[C][R] = in[R][C] ----------------
__global__ void transpose_kernel(const float* __restrict__ in,
                                 float* __restrict__ out, int R, int C)
{
    __shared__ float tile[32][33];
    int x  = blockIdx.x * 32 + threadIdx.x;   // col in input
    int y0 = blockIdx.y * 32;
#pragma unroll
    for (int dy = threadIdx.y; dy < 32; dy += 8)
        tile[dy][threadIdx.x] = in[(size_t)(y0 + dy) * C + x];
    __syncthreads();
    int ox = y0 + threadIdx.x;                // col in output
    int oy0 = blockIdx.x * 32;
#pragma unroll
    for (int dy = threadIdx.y; dy < 32; dy += 8)
        out[(size_t)(oy0 + dy) * R + ox] = tile[threadIdx.x][dy];
}

// ---------------- zero vector ----------------
__global__ void zero_kernel(float* __restrict__ p, int n)
{
    int i = blockIdx.x * blockDim.x + threadIdx.x;
    if (i < n) p[i] = 0.0f;
}

// ---------------- Sinkhorn row step: r[i] = LSE_j(S[i,j] - c[j]) ----------------
__global__ __launch_bounds__(256)
void row_lse_kernel(const float* __restrict__ S, const float* __restrict__ c,
                    float* __restrict__ r)
{
    const size_t i = blockIdx.x;
    const float4* row = (const float4*)(S + i * NR);
    const float4* c4  = (const float4*)c;
    float m = -INFINITY, s = 0.0f;
    for (int j = threadIdx.x; j < NR / 4; j += 256) {
        float4 v  = row[j];
        float4 cc = c4[j];
        lse_add(m, s, v.x - cc.x);
        lse_add(m, s, v.y - cc.y);
        lse_add(m, s, v.z - cc.z);
        lse_add(m, s, v.w - cc.w);
    }
    __shared__ float sm[256], ss[256];
    sm[threadIdx.x] = m; ss[threadIdx.x] = s;
    __syncthreads();
    for (int off = 128; off > 0; off >>= 1) {
        if (threadIdx.x < off)
            lse_merge(sm[threadIdx.x], ss[threadIdx.x],
                      sm[threadIdx.x + off], ss[threadIdx.x + off]);
        __syncthreads();
    }
    if (threadIdx.x == 0) r[i] = sm[0] + logf(ss[0]);
}

// ---------------- Sinkhorn col step, phase 1: partial LSE over row chunks ----------------
__global__ __launch_bounds__(256)
void col_partial_kernel(const float* __restrict__ S, const float* __restrict__ r,
                        float* __restrict__ pm, float* __restrict__ ps)
{
    const int j  = blockIdx.x * 256 + threadIdx.x;   // column
    const int i0 = blockIdx.y * ROWS_PER_CHUNK;
    float m = -INFINITY, s = 0.0f;
#pragma unroll 4
    for (int i = i0; i < i0 + ROWS_PER_CHUNK; ++i) {
        float v = S[(size_t)i * NR + j] - r[i];
        lse_add(m, s, v);
    }
    pm[(size_t)blockIdx.y * NR + j] = m;
    ps[(size_t)blockIdx.y * NR + j] = s;
}

// ---------------- Sinkhorn col step, phase 2: combine partials ----------------
__global__ __launch_bounds__(256)
void col_combine_kernel(const float* __restrict__ pm, const float* __restrict__ ps,
                        float* __restrict__ c)
{
    const int j = blockIdx.x * 256 + threadIdx.x;
    float m = -INFINITY, s = 0.0f;
#pragma unroll 8
    for (int ch = 0; ch < COL_CHUNKS; ++ch)
        lse_merge(m, s, pm[(size_t)ch * NR + j], ps[(size_t)ch * NR + j]);
    c[j] = m + logf(s);
}

// ---------------- output: out = exp(S - r_i - c_j) ----------------
__global__ __launch_bounds__(256)
void out_exp_kernel(const float* __restrict__ S, const float* __restrict__ r,
                    const float* __restrict__ c, float* __restrict__ out)
{
    const size_t nq = (size_t)NR * NR / 4;
    const float4* S4 = (const float4*)S;
    const float4* c4 = (const float4*)c;
    float4* o4 = (float4*)out;
    size_t idx = (size_t)blockIdx.x * blockDim.x + threadIdx.x;
    const size_t stride = (size_t)gridDim.x * blockDim.x;
    for (; idx < nq; idx += stride) {
        size_t i  = idx / (NR / 4);
        size_t jq = idx % (NR / 4);
        float ri = r[i];
        float4 cc = c4[jq];
        float4 v = S4[idx];
        float4 o;
        o.x = expf(v.x - ri - cc.x);
        o.y = expf(v.y - ri - cc.y);
        o.z = expf(v.z - ri - cc.z);
        o.w = expf(v.w - ri - cc.w);
        o4[idx] = o;
    }
}

// ---------------- launch ----------------
extern "C" void kernel_launch(void* const* d_in, const int* in_sizes, int n_in,
                              void* d_out, int out_size)
{
    const float* emb_a = (const float*)d_in[0];
    const float* emb_b = (const float*)d_in[1];
    const float* W1    = (const float*)d_in[2];
    const float* b1    = (const float*)d_in[3];
    const float* W2    = (const float*)d_in[4];
    const float* b2    = (const float*)d_in[5];
    float* out = (float*)d_out;

    float *scores, *h, *a, *b, *bT, *r, *c, *pm, *ps;
    cudaGetSymbolAddress((void**)&scores, g_scores);
    cudaGetSymbolAddress((void**)&h,  g_h);
    cudaGetSymbolAddress((void**)&a,  g_a);
    cudaGetSymbolAddress((void**)&b,  g_b);
    cudaGetSymbolAddress((void**)&bT, g_bT);
    cudaGetSymbolAddress((void**)&r,  g_r);
    cudaGetSymbolAddress((void**)&c,  g_c);
    cudaGetSymbolAddress((void**)&pm, g_pm);
    cudaGetSymbolAddress((void**)&ps, g_ps);

    dim3 gProj(DD / BN, NR / BM);     // (8, 64)
    dim3 gScore(NR / BN, NR / BM);    // (64, 64)

    // projections
    sgemm_kernel<1><<<gProj, 256>>>(NR, DD, DD, emb_a, W1, b1, h, 1.0f);
    sgemm_kernel<0><<<gProj, 256>>>(NR, DD, DD, h, W2, b2, a, 1.0f);
    sgemm_kernel<1><<<gProj, 256>>>(NR, DD, DD, emb_b, W1, b1, h, 1.0f);
    sgemm_kernel<0><<<gProj, 256>>>(NR, DD, DD, h, W2, b2, b, 1.0f);

    // transpose b -> bT [DD, NR]
    transpose_kernel<<<dim3(DD / 32, NR / 32), dim3(32, 8)>>>(b, bT, NR, DD);

    // scores = (a @ bT) * 20
    sgemm_kernel<0><<<gScore, 256>>>(NR, NR, DD, a, bT, nullptr, scores, INV_TEMP);

    // Sinkhorn in (r, c) offset form
    zero_kernel<<<NR / 256, 256>>>(c, NR);
    for (int it = 0; it < ITERS; ++it) {
        row_lse_kernel<<<NR, 256>>>(scores, c, r);
        col_partial_kernel<<<dim3(NR / 256, COL_CHUNKS), 256>>>(scores, r, pm, ps);
        col_combine_kernel<<<NR / 256, 256>>>(pm, ps, c);
    }

    // final output
    out_exp_kernel<<<2048, 256>>>(scores, r, c, out);
}

// round 4
// speedup vs baseline: 3.1819x; 3.1819x over previous
#include <cuda_runtime.h>
#include <cuda_fp16.h>
#include <math.h>
#include <stdint.h>

// Problem constants
#define NR 8192
#define DD 1024
#define ITERS 20
#define INV_TEMP 20.0f

// iteration-1 column pass chunking
#define COL_CHUNKS 64
#define ROWS_PER_CHUNK (NR / COL_CHUNKS)

// fast fused Sinkhorn iteration
#define FRPB 16
#define FNBLK (NR / FRPB)   // 512

// HMMA tiling: BM=128, BN=128, BK=32, 8 warps (2 M x 4 N), warp tile 64x32
#define HBK 32
#define ROWB 80                       // padded row stride in bytes (32 halfs + 8 pad)
#define TILEB (128 * ROWB)            // 10240 B per operand tile
#define BUFB (4 * TILEB)              // 40960 B per stage (Ahi,Alo,Bhi,Blo)
#define SMEM_HMMA (2 * BUFB)          // 81920 B double buffered

// ---------------- device scratch (static, no allocation) ----------------
__device__ float g_scores[(size_t)NR * NR];   // 256 MB
__device__ __half g_x_hi[(size_t)NR * DD];
__device__ __half g_x_lo[(size_t)NR * DD];
__device__ __half g_h_hi[(size_t)NR * DD];
__device__ __half g_h_lo[(size_t)NR * DD];
__device__ __half g_a_hi[(size_t)NR * DD];
__device__ __half g_a_lo[(size_t)NR * DD];
__device__ __half g_b_hi[(size_t)NR * DD];
__device__ __half g_b_lo[(size_t)NR * DD];
__device__ __half g_w1_hi[(size_t)DD * DD];
__device__ __half g_w1_lo[(size_t)DD * DD];
__device__ __half g_w2_hi[(size_t)DD * DD];
__device__ __half g_w2_lo[(size_t)DD * DD];
__device__ float g_r[NR];
__device__ float g_c[NR];
__device__ float g_pm[(size_t)COL_CHUNKS * NR];
__device__ float g_ps[(size_t)COL_CHUNKS * NR];
__device__ float g_part[(size_t)FNBLK * NR];  // 16 MB

// ---------------- small helpers ----------------
__device__ __forceinline__ uint32_t smem_to_u32(const void* smem_ptr) {
    uint32_t addr;
    asm("{ .reg .u64 tmp; cvta.to.shared.u64 tmp, %1; cvt.u32.u64 %0, tmp; }"
        : "=r"(addr) : "l"(smem_ptr));
    return addr;
}
__device__ __forceinline__ void cp16(uint32_t saddr, const void* g) {
    asm volatile("cp.async.cg.shared.global [%0], [%1], 16;" :: "r"(saddr), "l"(g));
}
__device__ __forceinline__ void cp_commit() {
    asm volatile("cp.async.commit_group;");
}
template <int N> __device__ __forceinline__ void cp_wait() {
    asm volatile("cp.async.wait_group %0;" :: "n"(N));
}
__device__ __forceinline__ void ldsm_x4(uint32_t* r, uint32_t addr) {
    asm volatile("ldmatrix.sync.aligned.m8n8.x4.shared.b16 {%0,%1,%2,%3}, [%4];"
                 : "=r"(r[0]), "=r"(r[1]), "=r"(r[2]), "=r"(r[3]) : "r"(addr));
}
__device__ __forceinline__ void ldsm_x2(uint32_t* r, uint32_t addr) {
    asm volatile("ldmatrix.sync.aligned.m8n8.x2.shared.b16 {%0,%1}, [%2];"
                 : "=r"(r[0]), "=r"(r[1]) : "r"(addr));
}
__device__ __forceinline__ void mma16816(float* c, const uint32_t* a, const uint32_t* b) {
    asm volatile(
        "mma.sync.aligned.m16n8k16.row.col.f32.f16.f16.f32 "
        "{%0,%1,%2,%3}, {%4,%5,%6,%7}, {%8,%9}, {%0,%1,%2,%3};"
        : "+f"(c[0]), "+f"(c[1]), "+f"(c[2]), "+f"(c[3])
        : "r"(a[0]), "r"(a[1]), "r"(a[2]), "r"(a[3]), "r"(b[0]), "r"(b[1]));
}
__device__ __forceinline__ float gelu_exact(float x) {
    return 0.5f * x * (1.0f + erff(x * 0.70710678118654752440f));
}
__device__ __forceinline__ void lse_add(float& m, float& s, float v) {
    if (v <= m) { s += __expf(v - m); }
    else        { s = s * __expf(m - v) + 1.0f; m = v; }
}
__device__ __forceinline__ void lse_merge(float& m1, float& s1, float m2, float s2) {
    if (m2 == -INFINITY) return;
    if (m1 == -INFINITY) { m1 = m2; s1 = s2; return; }
    if (m2 <= m1) { s1 += s2 * __expf(m2 - m1); }
    else { s1 = s1 * __expf(m1 - m2) + s2; m1 = m2; }
}

// ---------------- HMMA GEMM: C = epilogue(scale*(A @ B^T) [+ bias]) ----------------
// A: [M, K] as hi/lo half splits (row-major, K contiguous)
// B: [N, K] as hi/lo half splits (row-major, K contiguous)
// 2-split product: hh + hl + lh (fp32 accumulate)
// ACT: 1 = exact-erf GELU.  OUT_SPLIT: 1 = write hi/lo half pair arrays, 0 = write fp32 C.
template <int ACT, int OUT_SPLIT>
__global__ __launch_bounds__(256)
void hmma_kernel(const __half* __restrict__ Ah, const __half* __restrict__ Al,
                 const __half* __restrict__ Bh, const __half* __restrict__ Bl,
                 const float* __restrict__ bias,
                 float* __restrict__ Cf, __half* __restrict__ Chi, __half* __restrict__ Clo,
                 int ldc, int Kdim, float scale)
{
    extern __shared__ __align__(16) char smem[];
    const uint32_t sbase = smem_to_u32(smem);
    const int tid  = threadIdx.x;
    const int warp = tid >> 5;
    const int lane = tid & 31;
    const int wm = warp >> 2;       // 0..1 (64-row slab)
    const int wn = warp & 3;        // 0..3 (32-col slab)

    const int m0 = blockIdx.y * 128;
    const int n0 = blockIdx.x * 128;

    const __half* gsrc0 = Ah + (size_t)m0 * Kdim;
    const __half* gsrc1 = Al + (size_t)m0 * Kdim;
    const __half* gsrc2 = Bh + (size_t)n0 * Kdim;
    const __half* gsrc3 = Bl + (size_t)n0 * Kdim;

    float acc[4][4][4];
#pragma unroll
    for (int i = 0; i < 4; i++)
#pragma unroll
        for (int j = 0; j < 4; j++)
#pragma unroll
            for (int k = 0; k < 4; k++) acc[i][j][k] = 0.0f;

    const int nTiles = Kdim / HBK;

    // ---- async tile loader: 8 x 16B chunks per thread per stage ----
    auto issue = [&](int buf, int kt) {
#pragma unroll
        for (int j = 0; j < 8; j++) {
            const int tile = j >> 1;
            const int qq = (j & 1) * 256 + tid;
            const int r = qq >> 2;
            const int cch = qq & 3;
            const __half* g;
            if      (tile == 0) g = gsrc0 + (size_t)r * Kdim + kt + cch * 8;
            else if (tile == 1) g = gsrc1 + (size_t)r * Kdim + kt + cch * 8;
            else if (tile == 2) g = gsrc2 + (size_t)r * Kdim + kt + cch * 8;
            else                g = gsrc3 + (size_t)r * Kdim + kt + cch * 8;
            cp16(sbase + buf * BUFB + tile * TILEB + r * ROWB + cch * 16, g);
        }
        cp_commit();
    };

    issue(0, 0);

    for (int t = 0; t < nTiles; ++t) {
        if (t + 1 < nTiles) {
            issue((t + 1) & 1, (t + 1) * HBK);
            cp_wait<1>();
        } else {
            cp_wait<0>();
        }
        __syncthreads();

        const uint32_t bufb = sbase + (t & 1) * BUFB;
        const uint32_t aBhi = bufb;
        const uint32_t aBlo = bufb + TILEB;
        const uint32_t bBhi = bufb + 2 * TILEB;
        const uint32_t bBlo = bufb + 3 * TILEB;

        // per-lane ldmatrix address components
        const int arow = wm * 64 + (lane & 15);
        const int akof = (lane >> 4) * 8;
        const int brow = wn * 32 + (lane & 7);
        const int bkof = ((lane >> 3) & 1) * 8;

#pragma unroll
        for (int ks = 0; ks < HBK; ks += 16) {
            uint32_t bh[4][2], bl[4][2];
#pragma unroll
            for (int bn = 0; bn < 4; bn++) {
                const uint32_t off = (uint32_t)(brow + bn * 8) * ROWB + (ks + bkof) * 2;
                ldsm_x2(bh[bn], bBhi + off);
                ldsm_x2(bl[bn], bBlo + off);
            }
            uint32_t af[4][4];
#pragma unroll
            for (int am = 0; am < 4; am++) {
                const uint32_t off = (uint32_t)(arow + am * 16) * ROWB + (ks + akof) * 2;
                ldsm_x4(af[am], aBhi + off);
            }
#pragma unroll
            for (int am = 0; am < 4; am++)
#pragma unroll
                for (int bn = 0; bn < 4; bn++) {
                    mma16816(acc[am][bn], af[am], bh[bn]);   // hi*hi
                    mma16816(acc[am][bn], af[am], bl[bn]);   // hi*lo
                }
#pragma unroll
            for (int am = 0; am < 4; am++) {
                const uint32_t off = (uint32_t)(arow + am * 16) * ROWB + (ks + akof) * 2;
                ldsm_x4(af[am], aBlo + off);
            }
#pragma unroll
            for (int am = 0; am < 4; am++)
#pragma unroll
                for (int bn = 0; bn < 4; bn++)
                    mma16816(acc[am][bn], af[am], bh[bn]);   // lo*hi
        }
        __syncthreads();
    }

    // ---- epilogue ----
#pragma unroll
    for (int am = 0; am < 4; am++) {
#pragma unroll
        for (int bn = 0; bn < 4; bn++) {
            const int row = m0 + wm * 64 + am * 16 + (lane >> 2);
            const int col = n0 + wn * 32 + bn * 8 + (lane & 3) * 2;
            float v[4];
#pragma unroll
            for (int k = 0; k < 4; k++) v[k] = acc[am][bn][k] * scale;
            if (bias) {
                const float bx = bias[col], by = bias[col + 1];
                v[0] += bx; v[1] += by; v[2] += bx; v[3] += by;
            }
            if (ACT == 1) {
#pragma unroll
                for (int k = 0; k < 4; k++) v[k] = gelu_exact(v[k]);
            }
            if (OUT_SPLIT == 1) {
#pragma unroll
                for (int half_row = 0; half_row < 2; half_row++) {
                    const size_t base = (size_t)(row + half_row * 8) * ldc + col;
                    const float v0 = v[half_row * 2], v1 = v[half_row * 2 + 1];
                    const __half h0 = __float2half_rn(v0);
                    const __half h1 = __float2half_rn(v1);
                    __half2 hhi = __halves2half2(h0, h1);
                    __half2 hlo = __halves2half2(__float2half_rn(v0 - __half2float(h0)),
                                                 __float2half_rn(v1 - __half2float(h1)));
                    *(__half2*)(Chi + base) = hhi;
                    *(__half2*)(Clo + base) = hlo;
                }
            } else {
                *(float2*)(Cf + (size_t)row * ldc + col) = make_float2(v[0], v[1]);
                *(float2*)(Cf + (size_t)(row + 8) * ldc + col) = make_float2(v[2], v[3]);
            }
        }
    }
}

// ---------------- fp32 -> fp16 hi/lo split (elementwise) ----------------
__global__ __launch_bounds__(256)
void split_kernel(const float* __restrict__ in, __half* __restrict__ hi,
                  __half* __restrict__ lo, int n)
{
    int i = blockIdx.x * 256 + threadIdx.x;
    if (i < n) {
        float x = in[i];
        __half h = __float2half_rn(x);
        hi[i] = h;
        lo[i] = __float2half_rn(x - __half2float(h));
    }
}

// ---------------- W [K,N] fp32 -> transposed [N,K] hi/lo half splits ----------------
__global__ void splitT_kernel(const float* __restrict__ in,
                              __half* __restrict__ hi, __half* __restrict__ lo)
{
    __shared__ float tile[32][33];
    const int x = blockIdx.x * 32 + threadIdx.x;   // N index in input
#pragma unroll
    for (int dy = threadIdx.y; dy < 32; dy += 8)
        tile[dy][threadIdx.x] = in[(size_t)(blockIdx.y * 32 + dy) * DD + x];
    __syncthreads();
    const int k = blockIdx.y * 32 + threadIdx.x;   // K index in output (contiguous)
#pragma unroll
    for (int dy = threadIdx.y; dy < 32; dy += 8) {
        const int n = blockIdx.x * 32 + dy;
        const float v = tile[threadIdx.x][dy];
        const __half h = __float2half_rn(v);
        hi[(size_t)n * DD + k] = h;
        lo[(size_t)n * DD + k] = __float2half_rn(v - __half2float(h));
    }
}

// ---------------- zero vector ----------------
__global__ void zero_kernel(float* __restrict__ p, int n)
{
    int i = blockIdx.x * blockDim.x + threadIdx.x;
    if (i < n) p[i] = 0.0f;
}

// ---------------- iteration 1 (max-tracked LSE) ----------------
__global__ __launch_bounds__(256)
void row_lse_kernel(const float* __restrict__ S, const float* __restrict__ c,
                    float* __restrict__ r)
{
    const size_t i = blockIdx.x;
    const float4* row = (const float4*)(S + i * NR);
    const float4* c4  = (const float4*)c;
    float m = -INFINITY, s = 0.0f;
    for (int j = threadIdx.x; j < NR / 4; j += 256) {
        float4 v  = row[j];
        float4 cc = c4[j];
        lse_add(m, s, v.x - cc.x);
        lse_add(m, s, v.y - cc.y);
        lse_add(m, s, v.z - cc.z);
        lse_add(m, s, v.w - cc.w);
    }
    __shared__ float sm[256], ss[256];
    sm[threadIdx.x] = m; ss[threadIdx.x] = s;
    __syncthreads();
    for (int off = 128; off > 0; off >>= 1) {
        if (threadIdx.x < off)
            lse_merge(sm[threadIdx.x], ss[threadIdx.x],
                      sm[threadIdx.x + off], ss[threadIdx.x + off]);
        __syncthreads();
    }
    if (threadIdx.x == 0) r[i] = sm[0] + logf(ss[0]);
}

__global__ __launch_bounds__(256)
void col_partial_kernel(const float* __restrict__ S, const float* __restrict__ r,
                        float* __restrict__ pm, float* __restrict__ ps)
{
    const int j  = blockIdx.x * 256 + threadIdx.x;
    const int i0 = blockIdx.y * ROWS_PER_CHUNK;
    float m = -INFINITY, s = 0.0f;
#pragma unroll 4
    for (int i = i0; i < i0 + ROWS_PER_CHUNK; ++i) {
        float v = S[(size_t)i * NR + j] - r[i];
        lse_add(m, s, v);
    }
    pm[(size_t)blockIdx.y * NR + j] = m;
    ps[(size_t)blockIdx.y * NR + j] = s;
}

__global__ __launch_bounds__(256)
void col_combine_kernel(const float* __restrict__ pm, const float* __restrict__ ps,
                        float* __restrict__ c)
{
    const int j = blockIdx.x * 256 + threadIdx.x;
    float m = -INFINITY, s = 0.0f;
#pragma unroll 8
    for (int ch = 0; ch < COL_CHUNKS; ++ch)
        lse_merge(m, s, pm[(size_t)ch * NR + j], ps[(size_t)ch * NR + j]);
    c[j] = m + logf(s);
}

// ---------------- fused fast iteration (iterations 2..20) ----------------
// After iteration 1's column update all entries exp(S - r - c) <= 1, so no
// max tracking needed: one streaming pass updates r and emits column partials.
__global__ __launch_bounds__(256)
void sink_iter_kernel(const float* __restrict__ S, float* __restrict__ r,
                      const float* __restrict__ c, float* __restrict__ part)
{
    __shared__ float sc[NR];
    __shared__ float red[8];
    __shared__ float stot;
    const int tid = threadIdx.x;

    for (int j = tid; j < NR / 4; j += 256)
        ((float4*)sc)[j] = ((const float4*)c)[j];
    __syncthreads();

    float4 acc[8];
#pragma unroll
    for (int k = 0; k < 8; ++k) acc[k] = make_float4(0.f, 0.f, 0.f, 0.f);

    const int i0 = blockIdx.x * FRPB;
    for (int ii = 0; ii < FRPB; ++ii) {
        const int i = i0 + ii;
        const float ri = __ldg(&r[i]);
        const float4* row = (const float4*)(S + (size_t)i * NR);
        float4 e[8];
        float s = 0.0f;
#pragma unroll
        for (int k = 0; k < 8; ++k) {
            float4 v  = row[tid + 256 * k];
            float4 cc = ((const float4*)sc)[tid + 256 * k];
            e[k].x = __expf(v.x - cc.x - ri);
            e[k].y = __expf(v.y - cc.y - ri);
            e[k].z = __expf(v.z - cc.z - ri);
            e[k].w = __expf(v.w - cc.w - ri);
            s += (e[k].x + e[k].y) + (e[k].z + e[k].w);
        }
#pragma unroll
        for (int o = 16; o > 0; o >>= 1) s += __shfl_xor_sync(0xffffffffu, s, o);
        if ((tid & 31) == 0) red[tid >> 5] = s;
        __syncthreads();
        if (tid == 0) {
            float t = 0.0f;
#pragma unroll
            for (int w = 0; w < 8; ++w) t += red[w];
            stot = t;
            r[i] = ri + logf(t);
        }
        __syncthreads();
        const float inv = 1.0f / stot;
#pragma unroll
        for (int k = 0; k < 8; ++k) {
            acc[k].x += e[k].x * inv;
            acc[k].y += e[k].y * inv;
            acc[k].z += e[k].z * inv;
            acc[k].w += e[k].w * inv;
        }
    }
    float4* p = (float4*)(part + (size_t)blockIdx.x * NR);
#pragma unroll
    for (int k = 0; k < 8; ++k) p[tid + 256 * k] = acc[k];
}

__global__ __launch_bounds__(256)
void sink_combine_kernel(const float* __restrict__ part, float* __restrict__ c)
{
    const int j = blockIdx.x * 256 + threadIdx.x;
    float s = 0.0f;
#pragma unroll 8
    for (int b = 0; b < FNBLK; ++b) s += part[(size_t)b * NR + j];
    c[j] += logf(s);
}

// ---------------- output: out = exp(S - r_i - c_j) ----------------
__global__ __launch_bounds__(256)
void out_exp_kernel(const float* __restrict__ S, const float* __restrict__ r,
                    const float* __restrict__ c, float* __restrict__ out)
{
    const size_t nq = (size_t)NR * NR / 4;
    const float4* S4 = (const float4*)S;
    const float4* c4 = (const float4*)c;
    float4* o4 = (float4*)out;
    size_t idx = (size_t)blockIdx.x * blockDim.x + threadIdx.x;
    const size_t stride = (size_t)gridDim.x * blockDim.x;
    for (; idx < nq; idx += stride) {
        size_t i  = idx / (NR / 4);
        size_t jq = idx % (NR / 4);
        float ri = r[i];
        float4 cc = c4[jq];
        float4 v = S4[idx];
        float4 o;
        o.x = __expf(v.x - ri - cc.x);
        o.y = __expf(v.y - ri - cc.y);
        o.z = __expf(v.z - ri - cc.z);
        o.w = __expf(v.w - ri - cc.w);
        o4[idx] = o;
    }
}

// ---------------- launch ----------------
extern "C" void kernel_launch(void* const* d_in, const int* in_sizes, int n_in,
                              void* d_out, int out_size)
{
    const float* emb_a = (const float*)d_in[0];
    const float* emb_b = (const float*)d_in[1];
    const float* W1    = (const float*)d_in[2];
    const float* b1    = (const float*)d_in[3];
    const float* W2    = (const float*)d_in[4];
    const float* b2    = (const float*)d_in[5];
    float* out = (float*)d_out;

    float *scores, *r, *c, *pm, *ps, *part;
    __half *x_hi, *x_lo, *h_hi, *h_lo, *a_hi, *a_lo, *b_hi, *b_lo;
    __half *w1_hi, *w1_lo, *w2_hi, *w2_lo;
    cudaGetSymbolAddress((void**)&scores, g_scores);
    cudaGetSymbolAddress((void**)&x_hi, g_x_hi);
    cudaGetSymbolAddress((void**)&x_lo, g_x_lo);
    cudaGetSymbolAddress((void**)&h_hi, g_h_hi);
    cudaGetSymbolAddress((void**)&h_lo, g_h_lo);
    cudaGetSymbolAddress((void**)&a_hi, g_a_hi);
    cudaGetSymbolAddress((void**)&a_lo, g_a_lo);
    cudaGetSymbolAddress((void**)&b_hi, g_b_hi);
    cudaGetSymbolAddress((void**)&b_lo, g_b_lo);
    cudaGetSymbolAddress((void**)&w1_hi, g_w1_hi);
    cudaGetSymbolAddress((void**)&w1_lo, g_w1_lo);
    cudaGetSymbolAddress((void**)&w2_hi, g_w2_hi);
    cudaGetSymbolAddress((void**)&w2_lo, g_w2_lo);
    cudaGetSymbolAddress((void**)&r,  g_r);
    cudaGetSymbolAddress((void**)&c,  g_c);
    cudaGetSymbolAddress((void**)&pm, g_pm);
    cudaGetSymbolAddress((void**)&ps, g_ps);
    cudaGetSymbolAddress((void**)&part, g_part);

    cudaFuncSetAttribute(hmma_kernel<1, 1>,
                         cudaFuncAttributeMaxDynamicSharedMemorySize, SMEM_HMMA);
    cudaFuncSetAttribute(hmma_kernel<0, 1>,
                         cudaFuncAttributeMaxDynamicSharedMemorySize, SMEM_HMMA);
    cudaFuncSetAttribute(hmma_kernel<0, 0>,
                         cudaFuncAttributeMaxDynamicSharedMemorySize, SMEM_HMMA);

    const int nel = NR * DD;
    const dim3 gProj(DD / 128, NR / 128);     // (8, 64)
    const dim3 gScore(NR / 128, NR / 128);    // (64, 64)

    // weight split + transpose to [N, K]
    splitT_kernel<<<dim3(32, 32), dim3(32, 8)>>>(W1, w1_hi, w1_lo);
    splitT_kernel<<<dim3(32, 32), dim3(32, 8)>>>(W2, w2_hi, w2_lo);

    // branch a: emb_a -> gelu(xW1+b1) -> (hW2+b2) as splits
    split_kernel<<<nel / 256, 256>>>(emb_a, x_hi, x_lo, nel);
    hmma_kernel<1, 1><<<gProj, 256, SMEM_HMMA>>>(x_hi, x_lo, w1_hi, w1_lo, b1,
                                                 nullptr, h_hi, h_lo, DD, DD, 1.0f);
    hmma_kernel<0, 1><<<gProj, 256, SMEM_HMMA>>>(h_hi, h_lo, w2_hi, w2_lo, b2,
                                                 nullptr, a_hi, a_lo, DD, DD, 1.0f);
    // branch b
    split_kernel<<<nel / 256, 256>>>(emb_b, x_hi, x_lo, nel);
    hmma_kernel<1, 1><<<gProj, 256, SMEM_HMMA>>>(x_hi, x_lo, w1_hi, w1_lo, b1,
                                                 nullptr, h_hi, h_lo, DD, DD, 1.0f);
    hmma_kernel<0, 1><<<gProj, 256, SMEM_HMMA>>>(h_hi, h_lo, w2_hi, w2_lo, b2,
                                                 nullptr, b_hi, b_lo, DD, DD, 1.0f);

    // scores = 20 * a @ b^T
    hmma_kernel<0, 0><<<gScore, 256, SMEM_HMMA>>>(a_hi, a_lo, b_hi, b_lo, nullptr,
                                                  scores, nullptr, nullptr, NR, DD,
                                                  INV_TEMP);

    // Sinkhorn iteration 1 (max-tracked)
    zero_kernel<<<NR / 256, 256>>>(c, NR);
    row_lse_kernel<<<NR, 256>>>(scores, c, r);
    col_partial_kernel<<<dim3(NR / 256, COL_CHUNKS), 256>>>(scores, r, pm, ps);
    col_combine_kernel<<<NR / 256, 256>>>(pm, ps, c);

    // iterations 2..20: fused single-pass
    for (int it = 1; it < ITERS; ++it) {
        sink_iter_kernel<<<FNBLK, 256>>>(scores, r, c, part);
        sink_combine_kernel<<<NR / 256, 256>>>(part, c);
    }

    // final output
    out_exp_kernel<<<2048, 256>>>(scores, r, c, out);
}